// round 16
// baseline (speedup 1.0000x reference)
#include <cuda_runtime.h>
#include <cstddef>

#define B_    8
#define N_    16384
#define NB    (B_ * N_)
#define L2E_  1.4426950408889634f
#define LN2_  0.6931471805599453f

// Ping-pong activation buffers (B, N, 16) fp32 — 8 MB each, both L2-resident.
__device__ float g_bufA[NB * 16];
__device__ float g_bufB[NB * 16];

static __device__ __forceinline__ float ex2f_(float x){ float y; asm("ex2.approx.f32 %0, %1;" : "=f"(y) : "f"(x)); return y; }
static __device__ __forceinline__ float rcpf_(float x){ float y; asm("rcp.approx.f32 %0, %1;" : "=f"(y) : "f"(x)); return y; }
static __device__ __forceinline__ float lg2f_(float x){ float y; asm("lg2.approx.f32 %0, %1;" : "=f"(y) : "f"(x)); return y; }

// Accurate tanh/sigmoid via ex2+rcp (rel err ~1e-6), overflow-safe.
static __device__ __forceinline__ float tanh_acc(float x){
    float e = fminf(fmaxf(-2.f * L2E_ * x, -80.f), 80.f);
    float t = ex2f_(e);
    return (1.f - t) * rcpf_(1.f + t);
}
static __device__ __forceinline__ float sig_acc(float x){
    float e = fminf(fmaxf(-L2E_ * x, -80.f), 80.f);
    return rcpf_(1.f + ex2f_(e));
}

// Packed f32x2 FMA: d = a*b + d  (SASS FFMA2 — PTX-only pattern on sm_103a)
static __device__ __forceinline__ void ffma2(float2& d, float2 a, float2 b){
    asm("fma.rn.f32x2 %0, %1, %2, %0;"
        : "+l"(*reinterpret_cast<unsigned long long*>(&d))
        : "l"(*reinterpret_cast<const unsigned long long*>(&a)),
          "l"(*reinterpret_cast<const unsigned long long*>(&b)));
}
static __device__ __forceinline__ float2 bcast2(float x){ return make_float2(x, x); }

// Volatile vector load: defeats CSE so a late re-read doesn't pin registers.
static __device__ __forceinline__ float4 ldg4v(const float* p){
    float4 v;
    asm volatile("ld.global.v4.f32 {%0,%1,%2,%3}, [%4];"
        : "=f"(v.x), "=f"(v.y), "=f"(v.z), "=f"(v.w) : "l"(p));
    return v;
}

// ---------------------------------------------------------------------------
// Layer 0: h = causal_conv(x/32768, W0, d=1) + b0 ; inp = x/32768 + h
// ---------------------------------------------------------------------------
__global__ __launch_bounds__(256) void layer0_k(
    const float* __restrict__ x, const float* __restrict__ W0,
    const float* __restrict__ b0, float* __restrict__ out)
{
    int idx = blockIdx.x * 256 + threadIdx.x;      // b*N + n
    int n = idx & (N_ - 1);
    float xc = x[idx] * (1.f / 32768.f);
    float xp = (n > 0) ? x[idx - 1] * (1.f / 32768.f) : 0.f;
    float y[16];
#pragma unroll
    for (int c = 0; c < 16; c++)
        y[c] = xc + (W0[2*c] * xp + W0[2*c + 1] * xc + b0[c]);
    float4* po = (float4*)(out + (size_t)idx * 16);
    po[0] = make_float4(y[0],  y[1],  y[2],  y[3]);
    po[1] = make_float4(y[4],  y[5],  y[6],  y[7]);
    po[2] = make_float4(y[8],  y[9],  y[10], y[11]);
    po[3] = make_float4(y[12], y[13], y[14], y[15]);
}

// ---------------------------------------------------------------------------
// Gated layer, T=2 timesteps per thread (packed f32x2).
// Each weight LDS.128 feeds 4 FFMA2 (2 output-pairs x 2 timesteps), halving
// L1/LSU wavefront load per timestep vs the T=1 version (which profiled
// L1=61.7% binding). Phase order keeps registers bounded:
//   k=1 taps (xc) -> xc dies -> k=0 taps (xp) -> nonlinearity -> Wr ->
//   volatile reload of xc for the residual add.
// ---------------------------------------------------------------------------
__global__ __launch_bounds__(128) void layer_k(
    const float* __restrict__ in, float* __restrict__ out,
    const float* __restrict__ Wf, const float* __restrict__ bf,
    const float* __restrict__ Wg, const float* __restrict__ bg,
    const float* __restrict__ Wr, const float* __restrict__ br, int d)
{
    __shared__ float4 wfg[2][16][8];     // [k][c][op]: {f_2op,f_2op+1,g_2op,g_2op+1}
    __shared__ float4 wr4[16][4];        // [c][q]: Wr[4q..4q+3, c]
    __shared__ float4 sbfg[8];           // {bf[2op],bf[2op+1],bg[2op],bg[2op+1]}
    __shared__ float2 sbr2[8];

    int tid = threadIdx.x;
    for (int i = tid; i < 256; i += 128){
        int k = i >> 7, c = (i >> 3) & 15, op = i & 7;
        int o0 = 2 * op;
        wfg[k][c][op] = make_float4(Wf[(o0    ) * 32 + c * 2 + k],
                                    Wf[(o0 + 1) * 32 + c * 2 + k],
                                    Wg[(o0    ) * 32 + c * 2 + k],
                                    Wg[(o0 + 1) * 32 + c * 2 + k]);
    }
    for (int i = tid; i < 64; i += 128){
        int c = i >> 2, q = i & 3;
        int o0 = 4 * q;
        wr4[c][q] = make_float4(Wr[(o0    ) * 16 + c], Wr[(o0 + 1) * 16 + c],
                                Wr[(o0 + 2) * 16 + c], Wr[(o0 + 3) * 16 + c]);
    }
    if (tid < 8){
        int o0 = 2 * tid;
        sbfg[tid] = make_float4(bf[o0], bf[o0 + 1], bg[o0], bg[o0 + 1]);
        sbr2[tid] = make_float2(br[o0], br[o0 + 1]);
    }
    __syncthreads();

    int t   = blockIdx.x * 128 + tid;         // timestep-pair index
    int b   = t >> 13;                        // t / (N/2), N/2 = 8192
    int n0  = (t & 8191) << 1;                // local n of first timestep
    size_t idx0 = ((size_t)b << 14) + n0;     // b*N + n0

    // accumulators: [ts][output-pair]
    float2 f2[2][8], g2[2][8];
#pragma unroll
    for (int op = 0; op < 8; op++){
        float4 bv = sbfg[op];
        f2[0][op] = make_float2(bv.x, bv.y); f2[1][op] = make_float2(bv.x, bv.y);
        g2[0][op] = make_float2(bv.z, bv.w); g2[1][op] = make_float2(bv.z, bv.w);
    }

    // ---- k=1 taps: current samples (32 consecutive floats) ----
    {
        float xc[2][16];
        const float4* pc = (const float4*)(in + idx0 * 16);
#pragma unroll
        for (int q = 0; q < 8; q++){
            float4 v = pc[q];
            int tt = q >> 2, c0 = (q & 3) * 4;
            xc[tt][c0] = v.x; xc[tt][c0+1] = v.y; xc[tt][c0+2] = v.z; xc[tt][c0+3] = v.w;
        }
#pragma unroll
        for (int c = 0; c < 16; c++){
            float2 x0 = bcast2(xc[0][c]);
            float2 x1 = bcast2(xc[1][c]);
#pragma unroll
            for (int op = 0; op < 8; op++){
                float4 w = wfg[1][c][op];
                float2 wf2 = make_float2(w.x, w.y), wg2 = make_float2(w.z, w.w);
                ffma2(f2[0][op], wf2, x0);
                ffma2(g2[0][op], wg2, x0);
                ffma2(f2[1][op], wf2, x1);
                ffma2(g2[1][op], wg2, x1);
            }
        }
    }

    // ---- k=0 taps: dilated past samples ----
    {
        float xp[2][16];
#pragma unroll
        for (int tt = 0; tt < 2; tt++){
            if (n0 + tt >= d){
                const float4* pp = (const float4*)(in + (idx0 + tt - d) * 16);
#pragma unroll
                for (int q = 0; q < 4; q++){
                    float4 v = pp[q];
                    xp[tt][4*q] = v.x; xp[tt][4*q+1] = v.y;
                    xp[tt][4*q+2] = v.z; xp[tt][4*q+3] = v.w;
                }
            } else {
#pragma unroll
                for (int c = 0; c < 16; c++) xp[tt][c] = 0.f;
            }
        }
#pragma unroll
        for (int c = 0; c < 16; c++){
            float2 x0 = bcast2(xp[0][c]);
            float2 x1 = bcast2(xp[1][c]);
#pragma unroll
            for (int op = 0; op < 8; op++){
                float4 w = wfg[0][c][op];
                float2 wf2 = make_float2(w.x, w.y), wg2 = make_float2(w.z, w.w);
                ffma2(f2[0][op], wf2, x0);
                ffma2(g2[0][op], wg2, x0);
                ffma2(f2[1][op], wf2, x1);
                ffma2(g2[1][op], wg2, x1);
            }
        }
    }

    // ---- gated nonlinearity ----
    float z[2][16];
#pragma unroll
    for (int tt = 0; tt < 2; tt++)
#pragma unroll
        for (int op = 0; op < 8; op++){
            z[tt][2*op]   = tanh_acc(f2[tt][op].x) * sig_acc(g2[tt][op].x);
            z[tt][2*op+1] = tanh_acc(f2[tt][op].y) * sig_acc(g2[tt][op].y);
        }

    // ---- out = Wr@z + br ----
    float2 r2[2][8];
#pragma unroll
    for (int op = 0; op < 8; op++){ r2[0][op] = sbr2[op]; r2[1][op] = sbr2[op]; }
#pragma unroll
    for (int c = 0; c < 16; c++){
        float2 z0 = bcast2(z[0][c]);
        float2 z1 = bcast2(z[1][c]);
#pragma unroll
        for (int q = 0; q < 4; q++){
            float4 w = wr4[c][q];
            float2 wa = make_float2(w.x, w.y), wb = make_float2(w.z, w.w);
            ffma2(r2[0][2*q],     wa, z0);
            ffma2(r2[0][2*q + 1], wb, z0);
            ffma2(r2[1][2*q],     wa, z1);
            ffma2(r2[1][2*q + 1], wb, z1);
        }
    }

    // ---- residual add (volatile reload of xc — L1 hit) + store ----
    float4* po = (float4*)(out + idx0 * 16);
#pragma unroll
    for (int tt = 0; tt < 2; tt++){
        const float* pc = in + (idx0 + tt) * 16;
#pragma unroll
        for (int q = 0; q < 4; q++){
            float4 v = ldg4v(pc + 4 * q);
            float2 ra = r2[tt][2*q], rb = r2[tt][2*q + 1];
            po[tt * 4 + q] = make_float4(v.x + ra.x, v.y + ra.y,
                                         v.z + rb.x, v.w + rb.y);
        }
    }
}

// ---------------------------------------------------------------------------
// Head: skip = relu(inp_final - x/32768); a = relu(Wa@skip + ba);
//       o = Wo@a + bo; logp = log_softmax(o); masked write (B, 256, N).
// Block = 512 threads (16 warps), tile = 64 timesteps, 4 per warp. Packed FMA.
// ---------------------------------------------------------------------------
#define HEAD_SMEM_FLOATS (16384 + 64*17 + 64*17 + 16*256 + 256*65)
#define HEAD_SMEM_BYTES  (HEAD_SMEM_FLOATS * 4)

__global__ __launch_bounds__(512) void head_k(
    const float* __restrict__ inpf, const float* __restrict__ x,
    const int* __restrict__ lengths,
    const float* __restrict__ Wa, const float* __restrict__ ba,
    const float* __restrict__ Wo, const float* __restrict__ bo,
    float* __restrict__ outp)
{
    extern __shared__ float sm[];
    float* WO = sm;                    // [64][256]  WO[k*256+o]
    float* WA = WO + 16384;            // [64][17]
    float* SK = WA + 64 * 17;          // [64][17]   relu(skip)
    float* AS = SK + 64 * 17;          // [16 warps][4 t][64]
    float* ST = AS + 16 * 256;         // [256][65]  logp staging

    int tid = threadIdx.x;
    int bId = blockIdx.x;
    int b  = bId >> 8;                 // 256 tiles of 64 per batch
    int n0 = (bId & 255) << 6;

    for (int i = tid; i < 256 * 64; i += 512){
        int o = i >> 6, k = i & 63;
        WO[k * 256 + o] = Wo[i];
    }
    for (int i = tid; i < 64 * 16; i += 512){
        int o = i >> 4, c = i & 15;
        WA[o * 17 + c] = Wa[i];
    }
    for (int i = tid; i < 64 * 16; i += 512){
        int nl = i >> 4, c = i & 15;
        float x0 = x[b * N_ + n0 + nl] * (1.f / 32768.f);
        float v = inpf[((size_t)(b * N_ + n0 + nl)) * 16 + c] - x0;
        SK[nl * 17 + c] = fmaxf(v, 0.f);
    }
    __syncthreads();

    int w = tid >> 5, l = tid & 31;

    // a = relu(Wa @ skip + ba) for this warp's 4 timesteps
#pragma unroll
    for (int t = 0; t < 4; t++){
        int nl = (w << 2) + t;
        float a0 = ba[l], a1 = ba[l + 32];
#pragma unroll
        for (int c = 0; c < 16; c++){
            float s = SK[nl * 17 + c];
            a0 += WA[l * 17 + c] * s;
            a1 += WA[(l + 32) * 17 + c] * s;
        }
        AS[w * 256 + t * 64 + l]      = fmaxf(a0, 0.f);
        AS[w * 256 + t * 64 + l + 32] = fmaxf(a1, 0.f);
    }
    __syncwarp();

    // logits: lane owns o = 4l..4l+3 (accA*) and o = 128+4l..128+4l+3 (accB*)
    float2 accA0[4], accA1[4], accB0[4], accB1[4];
    {
        float4 bA = *(const float4*)(bo + l * 4);
        float4 bB = *(const float4*)(bo + 128 + l * 4);
#pragma unroll
        for (int t = 0; t < 4; t++){
            accA0[t] = make_float2(bA.x, bA.y); accA1[t] = make_float2(bA.z, bA.w);
            accB0[t] = make_float2(bB.x, bB.y); accB1[t] = make_float2(bB.z, bB.w);
        }
    }
#pragma unroll 4
    for (int k = 0; k < 64; k++){
        float4 w0 = *(const float4*)&WO[k * 256 + l * 4];         // conflict-free
        float4 w1 = *(const float4*)&WO[k * 256 + 128 + l * 4];
        float2 w0a = make_float2(w0.x, w0.y), w0b = make_float2(w0.z, w0.w);
        float2 w1a = make_float2(w1.x, w1.y), w1b = make_float2(w1.z, w1.w);
#pragma unroll
        for (int t = 0; t < 4; t++){
            float2 av = bcast2(AS[w * 256 + t * 64 + k]);         // broadcast
            ffma2(accA0[t], w0a, av);
            ffma2(accA1[t], w0b, av);
            ffma2(accB0[t], w1a, av);
            ffma2(accB1[t], w1b, av);
        }
    }

    // per-timestep log-softmax over 256 (warp-wide), stage [o][nl]
#pragma unroll
    for (int t = 0; t < 4; t++){
        int nl = (w << 2) + t;
        float va0 = accA0[t].x, va1 = accA0[t].y, va2 = accA1[t].x, va3 = accA1[t].y;
        float vb0 = accB0[t].x, vb1 = accB0[t].y, vb2 = accB1[t].x, vb3 = accB1[t].y;
        float m = fmaxf(fmaxf(fmaxf(va0, va1), fmaxf(va2, va3)),
                        fmaxf(fmaxf(vb0, vb1), fmaxf(vb2, vb3)));
#pragma unroll
        for (int off = 16; off; off >>= 1)
            m = fmaxf(m, __shfl_xor_sync(0xffffffffu, m, off));
        float s = ex2f_((va0 - m) * L2E_) + ex2f_((va1 - m) * L2E_)
                + ex2f_((va2 - m) * L2E_) + ex2f_((va3 - m) * L2E_)
                + ex2f_((vb0 - m) * L2E_) + ex2f_((vb1 - m) * L2E_)
                + ex2f_((vb2 - m) * L2E_) + ex2f_((vb3 - m) * L2E_);
#pragma unroll
        for (int off = 16; off; off >>= 1)
            s += __shfl_xor_sync(0xffffffffu, s, off);
        float lse = lg2f_(s) * LN2_ + m;
        ST[(4 * l + 0) * 65 + nl] = va0 - lse;
        ST[(4 * l + 1) * 65 + nl] = va1 - lse;
        ST[(4 * l + 2) * 65 + nl] = va2 - lse;
        ST[(4 * l + 3) * 65 + nl] = va3 - lse;
        ST[(128 + 4 * l + 0) * 65 + nl] = vb0 - lse;
        ST[(128 + 4 * l + 1) * 65 + nl] = vb1 - lse;
        ST[(128 + 4 * l + 2) * 65 + nl] = vb2 - lse;
        ST[(128 + 4 * l + 3) * 65 + nl] = vb3 - lse;
    }
    __syncthreads();

    // coalesced masked write to (B, 256, N)
    int len = lengths[b];
    for (int i = tid; i < 256 * 64; i += 512){
        int o = i >> 6, nl = i & 63;
        int n = n0 + nl;
        float v = (n < len) ? ST[o * 65 + nl] : 0.f;
        outp[((size_t)(b * 256 + o)) * N_ + n] = v;
    }
}

// ---------------------------------------------------------------------------
extern "C" void kernel_launch(void* const* d_in, const int* in_sizes, int n_in,
                              void* d_out, int out_size)
{
    const float* x  = (const float*)d_in[0];
    const int* lengths = (const int*)d_in[1];
    const float* W0 = (const float*)d_in[2];
    const float* b0 = (const float*)d_in[3];
    const float* Wf = (const float*)d_in[4];
    const float* bf = (const float*)d_in[5];
    const float* Wg = (const float*)d_in[6];
    const float* bg = (const float*)d_in[7];
    const float* Wr = (const float*)d_in[8];
    const float* br = (const float*)d_in[9];
    const float* Wa = (const float*)d_in[10];
    const float* ba = (const float*)d_in[11];
    const float* Wo = (const float*)d_in[12];
    const float* bo = (const float*)d_in[13];
    float* out = (float*)d_out;

    float *bufA, *bufB;
    cudaGetSymbolAddress((void**)&bufA, g_bufA);
    cudaGetSymbolAddress((void**)&bufB, g_bufB);

    cudaFuncSetAttribute(head_k, cudaFuncAttributeMaxDynamicSharedMemorySize,
                         HEAD_SMEM_BYTES);

    layer0_k<<<NB / 256, 256>>>(x, W0, b0, bufA);

    float* cur = bufA;
    float* nxt = bufB;
    for (int i = 1; i < 30; i++){
        int j = i - 1;
        int d = 1 << (i % 10);
        layer_k<<<NB / 2 / 128, 128>>>(cur, nxt,
                                       Wf + j * 512, bf + j * 16,
                                       Wg + j * 512, bg + j * 16,
                                       Wr + j * 256, br + j * 16, d);
        float* tmp = cur; cur = nxt; nxt = tmp;
    }

    head_k<<<B_ * (N_ / 64), 512, HEAD_SMEM_BYTES>>>(
        cur, x, lengths, Wa, ba, Wo, bo, out);
}